// round 1
// baseline (speedup 1.0000x reference)
#include <cuda_runtime.h>
#include <cuda_bf16.h>
#include <math.h>

// Problem constants (fixed shapes for this problem: N = 12288)
#define MAXN   12288
#define JS     12          // j-splits; JT = N/JS = 1024
#define MAXJT  1024
#define TPB    256
#define NEG_BIG (-1.0e30f)

// Scratch: per (split, i) the top-4 u-values (u = p_i . p_j - 0.5*|p_j|^2).
// JS * MAXN * 4 floats = 2.36 MB, static device global (no allocation).
__device__ float4 g_cand[JS * MAXN];

__device__ __forceinline__ void insert4(float u, float& m1, float& m2, float& m3, float& m4) {
    float t1 = fminf(u,  m1); m1 = fmaxf(u,  m1);
    float t2 = fminf(t1, m2); m2 = fmaxf(t1, m2);
    float t3 = fminf(t2, m3); m3 = fmaxf(t2, m3);
    m4 = fmaxf(t3, m4);
}

__global__ __launch_bounds__(TPB)
void nn_partial_kernel(const float* __restrict__ pts, int n) {
    __shared__ float4 sh[MAXJT];
    const int JT = n / JS;                  // 1024
    const int i  = blockIdx.x * TPB + threadIdx.x;
    const int j0 = blockIdx.y * JT;

    // Load this block's j-range into shared as {x, y, z, 0.5*|p|^2}
    for (int t = threadIdx.x; t < JT; t += TPB) {
        int j = j0 + t;
        float x = pts[3 * j + 0];
        float y = pts[3 * j + 1];
        float z = pts[3 * j + 2];
        sh[t] = make_float4(x, y, z, 0.5f * (x * x + y * y + z * z));
    }
    __syncthreads();

    const float xi = pts[3 * i + 0];
    const float yi = pts[3 * i + 1];
    const float zi = pts[3 * i + 2];

    float m1 = NEG_BIG, m2 = NEG_BIG, m3 = NEG_BIG, m4 = NEG_BIG;

    // i-tile (width 256) always lies entirely inside one j-split (width 1024):
    // block-uniform branch, no divergence.
    const bool hasSelf = ((int)(blockIdx.x * TPB) / JT) == (int)blockIdx.y;

    if (hasSelf) {
        // Track top-4 (self will be the max; dropped at merge).
        #pragma unroll 4
        for (int t = 0; t < JT; ++t) {
            float4 p = sh[t];
            float u = fmaf(zi, p.z, fmaf(yi, p.y, fmaf(xi, p.x, -p.w)));
            float t1 = fminf(u,  m1); m1 = fmaxf(u,  m1);
            float t2 = fminf(t1, m2); m2 = fmaxf(t1, m2);
            float t3 = fminf(t2, m3); m3 = fmaxf(t2, m3);
            m4 = fmaxf(t3, m4);
        }
    } else {
        // Self not in range: top-3 suffices (5 min/max per pair).
        #pragma unroll 4
        for (int t = 0; t < JT; ++t) {
            float4 p = sh[t];
            float u = fmaf(zi, p.z, fmaf(yi, p.y, fmaf(xi, p.x, -p.w)));
            float t1 = fminf(u,  m1); m1 = fmaxf(u,  m1);
            float t2 = fminf(t1, m2); m2 = fmaxf(t1, m2);
            m3 = fmaxf(t2, m3);
        }
    }

    g_cand[blockIdx.y * n + i] = make_float4(m1, m2, m3, m4);
}

__global__ __launch_bounds__(TPB)
void merge_cov_kernel(const float* __restrict__ pts,
                      const float* __restrict__ quat,
                      float* __restrict__ out, int n) {
    const int i = blockIdx.x * TPB + threadIdx.x;
    if (i >= n) return;

    // Merge the JS*4 candidates: global top-4 of u. m1 == self (d2 = 0).
    float m1 = NEG_BIG, m2 = NEG_BIG, m3 = NEG_BIG, m4 = NEG_BIG;
    #pragma unroll
    for (int s = 0; s < JS; ++s) {
        float4 c = g_cand[s * n + i];
        insert4(c.x, m1, m2, m3, m4);
        insert4(c.y, m1, m2, m3, m4);
        insert4(c.z, m1, m2, m3, m4);
        insert4(c.w, m1, m2, m3, m4);
    }

    const float xi = pts[3 * i + 0];
    const float yi = pts[3 * i + 1];
    const float zi = pts[3 * i + 2];
    const float sqi = xi * xi + yi * yi + zi * zi;

    // d2 = sqi - 2*u ; dist = sqrt(max(d2, 0))
    float d1 = sqrtf(fmaxf(fmaf(-2.0f, m2, sqi), 0.0f));
    float d2 = sqrtf(fmaxf(fmaf(-2.0f, m3, sqi), 0.0f));
    float d3 = sqrtf(fmaxf(fmaf(-2.0f, m4, sqi), 0.0f));
    float mean = (d1 + d2 + d3) * (1.0f / 3.0f);
    float s = 0.001f * fmaxf(mean, 1e-5f);

    // Normalized quaternion -> rotation
    float qr = quat[4 * i + 0];
    float qx = quat[4 * i + 1];
    float qy = quat[4 * i + 2];
    float qz = quat[4 * i + 3];
    float inv = rsqrtf(qr * qr + qx * qx + qy * qy + qz * qz);
    qr *= inv; qx *= inv; qy *= inv; qz *= inv;

    float R00 = 1.0f - 2.0f * (qy * qy + qz * qz);
    float R01 = 2.0f * (qx * qy - qr * qz);
    float R02 = 2.0f * (qx * qz + qr * qy);
    float R10 = 2.0f * (qx * qy + qr * qz);
    float R11 = 1.0f - 2.0f * (qx * qx + qz * qz);
    float R12 = 2.0f * (qy * qz - qr * qx);
    float R20 = 2.0f * (qx * qz - qr * qy);
    float R21 = 2.0f * (qy * qz + qr * qx);
    float R22 = 1.0f - 2.0f * (qx * qx + qy * qy);

    // M = s * R (isotropic scale); cov = M * M^T
    float M00 = s * R00, M01 = s * R01, M02 = s * R02;
    float M10 = s * R10, M11 = s * R11, M12 = s * R12;
    float M20 = s * R20, M21 = s * R21, M22 = s * R22;

    float c00 = M00 * M00 + M01 * M01 + M02 * M02;
    float c01 = M00 * M10 + M01 * M11 + M02 * M12;
    float c02 = M00 * M20 + M01 * M21 + M02 * M22;
    float c11 = M10 * M10 + M11 * M11 + M12 * M12;
    float c12 = M10 * M20 + M11 * M21 + M12 * M22;
    float c22 = M20 * M20 + M21 * M21 + M22 * M22;

    float* o = out + (size_t)i * 9;
    o[0] = c00; o[1] = c01; o[2] = c02;
    o[3] = c01; o[4] = c11; o[5] = c12;
    o[6] = c02; o[7] = c12; o[8] = c22;
}

extern "C" void kernel_launch(void* const* d_in, const int* in_sizes, int n_in,
                              void* d_out, int out_size) {
    const float* pts  = (const float*)d_in[0];   // (N, 3) float32
    const float* quat = (const float*)d_in[1];   // (N, 4) float32
    float* out = (float*)d_out;                  // (N, 3, 3) float32
    int n = in_sizes[0] / 3;                     // 12288

    dim3 grid1(n / TPB, JS);
    nn_partial_kernel<<<grid1, TPB>>>(pts, n);
    merge_cov_kernel<<<(n + TPB - 1) / TPB, TPB>>>(pts, quat, out, n);
}

// round 2
// speedup vs baseline: 1.1261x; 1.1261x over previous
#include <cuda_runtime.h>
#include <cuda_bf16.h>
#include <math.h>

// Fixed shapes: N = 12288
#define N_FIX   12288
#define JS      12            // j-splits
#define JT      1024          // N / JS
#define TPB     128
#define TILE_I  256           // i's per block (2 per thread)
#define GRIDX   48            // N / TILE_I
#define NEG_BIG (-1.0e30f)

// Scratch: per (split, i) sorted top-4 of u = p_i.p_j - 0.5|p_j|^2 (desc).
// Non-self splits leave slot 4 = NEG_BIG (still a valid sorted 4-list).
__device__ float4 g_cand[JS * N_FIX];
// Per-i-tile arrival counters for the fused merge (reset each replay by the merger).
__device__ int g_cnt[GRIDX];

// ---- branchless selection networks --------------------------------------

__device__ __forceinline__ void sort4_top3(float u0, float u1, float u2, float u3,
                                           float& s1, float& s2, float& s3) {
    float p1 = fmaxf(u0, u1), p2 = fminf(u0, u1);
    float q1 = fmaxf(u2, u3), q2 = fminf(u2, u3);
    s1 = fmaxf(p1, q1);
    float x = fminf(p1, q1);
    float y = fmaxf(p2, q2);
    s2 = fmaxf(x, y);
    s3 = fminf(x, y);
}

__device__ __forceinline__ void sort4_full(float u0, float u1, float u2, float u3,
                                           float& s1, float& s2, float& s3, float& s4) {
    float p1 = fmaxf(u0, u1), p2 = fminf(u0, u1);
    float q1 = fmaxf(u2, u3), q2 = fminf(u2, u3);
    s1 = fmaxf(p1, q1);
    float x = fminf(p1, q1);
    float y = fmaxf(p2, q2);
    s2 = fmaxf(x, y);
    s3 = fminf(x, y);
    s4 = fminf(p2, q2);          // min of the two pair-losers = overall min
}

// merge sorted m1>=m2>=m3 with sorted s1>=s2>=s3, keep top-3 (7 min/max)
__device__ __forceinline__ void merge3(float& m1, float& m2, float& m3,
                                       float s1, float s2, float s3) {
    float a = fmaxf(m1, s1), b = fminf(m1, s1);
    float c = fmaxf(m2, s2);
    float e = fmaxf(m3, s3);
    float t = fminf(b, c);
    m1 = a;
    m2 = fmaxf(b, c);
    m3 = fmaxf(t, e);
}

// merge sorted 4-lists, keep top-4 (13 min/max)
__device__ __forceinline__ void merge4(float& m1, float& m2, float& m3, float& m4,
                                       float s1, float s2, float s3, float s4) {
    float a = fmaxf(m1, s1), b = fminf(m1, s1);
    float c = fmaxf(m2, s2), d = fminf(m2, s2);
    float e = fmaxf(m3, s3);
    float g = fmaxf(m4, s4);
    float t  = fminf(b, c);
    float r2 = fmaxf(b, c);
    float r3 = fmaxf(t, e);
    float l1 = fminf(t, e);
    m1 = a;
    m2 = r2;
    m3 = r3;
    m4 = fmaxf(fmaxf(l1, d), g);
}

__device__ __forceinline__ float dot_u(float x, float y, float z, float4 p) {
    return fmaf(z, p.z, fmaf(y, p.y, fmaf(x, p.x, -p.w)));
}

// ---- fused kernel: partial top-k + last-block merge + covariance --------

__global__ __launch_bounds__(TPB)
void gauss_kernel(const float* __restrict__ pts,
                  const float* __restrict__ quat,
                  float* __restrict__ out, int n) {
    __shared__ float4 sh[JT];
    const int tile = blockIdx.x;
    const int sp   = blockIdx.y;
    const int j0   = sp * JT;
    const int i0   = tile * TILE_I + threadIdx.x;
    const int i1   = i0 + TPB;

    // Stage this split's points as {x, y, z, 0.5|p|^2}
    for (int t = threadIdx.x; t < JT; t += TPB) {
        int j = j0 + t;
        float x = pts[3 * j + 0];
        float y = pts[3 * j + 1];
        float z = pts[3 * j + 2];
        sh[t] = make_float4(x, y, z, 0.5f * (x * x + y * y + z * z));
    }
    __syncthreads();

    const float xa = pts[3 * i0 + 0], ya = pts[3 * i0 + 1], za = pts[3 * i0 + 2];
    const float xb = pts[3 * i1 + 0], yb = pts[3 * i1 + 1], zb = pts[3 * i1 + 2];

    float a1 = NEG_BIG, a2 = NEG_BIG, a3 = NEG_BIG, a4 = NEG_BIG;
    float b1 = NEG_BIG, b2 = NEG_BIG, b3 = NEG_BIG, b4 = NEG_BIG;

    // 256-wide i-tile always fully inside one 1024-wide j-split: uniform branch.
    const bool hasSelf = ((tile >> 2) == sp);

    if (hasSelf) {
        // Track top-4: self (global max of u) is dropped at merge time.
        #pragma unroll 2
        for (int t = 0; t < JT; t += 4) {
            float4 p0 = sh[t], p1 = sh[t + 1], p2 = sh[t + 2], p3 = sh[t + 3];
            {
                float u0 = dot_u(xa, ya, za, p0), u1 = dot_u(xa, ya, za, p1);
                float u2 = dot_u(xa, ya, za, p2), u3 = dot_u(xa, ya, za, p3);
                float s1, s2, s3, s4;
                sort4_full(u0, u1, u2, u3, s1, s2, s3, s4);
                merge4(a1, a2, a3, a4, s1, s2, s3, s4);
            }
            {
                float u0 = dot_u(xb, yb, zb, p0), u1 = dot_u(xb, yb, zb, p1);
                float u2 = dot_u(xb, yb, zb, p2), u3 = dot_u(xb, yb, zb, p3);
                float s1, s2, s3, s4;
                sort4_full(u0, u1, u2, u3, s1, s2, s3, s4);
                merge4(b1, b2, b3, b4, s1, s2, s3, s4);
            }
        }
    } else {
        #pragma unroll 2
        for (int t = 0; t < JT; t += 4) {
            float4 p0 = sh[t], p1 = sh[t + 1], p2 = sh[t + 2], p3 = sh[t + 3];
            {
                float u0 = dot_u(xa, ya, za, p0), u1 = dot_u(xa, ya, za, p1);
                float u2 = dot_u(xa, ya, za, p2), u3 = dot_u(xa, ya, za, p3);
                float s1, s2, s3;
                sort4_top3(u0, u1, u2, u3, s1, s2, s3);
                merge3(a1, a2, a3, s1, s2, s3);
            }
            {
                float u0 = dot_u(xb, yb, zb, p0), u1 = dot_u(xb, yb, zb, p1);
                float u2 = dot_u(xb, yb, zb, p2), u3 = dot_u(xb, yb, zb, p3);
                float s1, s2, s3;
                sort4_top3(u0, u1, u2, u3, s1, s2, s3);
                merge3(b1, b2, b3, s1, s2, s3);
            }
        }
    }

    g_cand[sp * n + i0] = make_float4(a1, a2, a3, a4);
    g_cand[sp * n + i1] = make_float4(b1, b2, b3, b4);

    // ---- last block per i-tile performs the merge + covariance ----
    __threadfence();                       // release g_cand writes
    __shared__ int s_last;
    if (threadIdx.x == 0)
        s_last = (atomicAdd(&g_cnt[tile], 1) == JS - 1) ? 1 : 0;
    __syncthreads();
    if (!s_last) return;
    __threadfence();                       // acquire other blocks' g_cand

    #pragma unroll
    for (int k = 0; k < 2; ++k) {
        const int i = tile * TILE_I + threadIdx.x + k * TPB;

        float4 c0 = g_cand[0 * n + i];
        float m1 = c0.x, m2 = c0.y, m3 = c0.z, m4 = c0.w;
        #pragma unroll
        for (int s = 1; s < JS; ++s) {
            float4 c = g_cand[s * n + i];
            merge4(m1, m2, m3, m4, c.x, c.y, c.z, c.w);
        }
        // m1 == self (u_self = 0.5|p_i|^2 is the strict global max); NNs: m2..m4

        const float xi = pts[3 * i + 0];
        const float yi = pts[3 * i + 1];
        const float zi = pts[3 * i + 2];
        const float sqi = xi * xi + yi * yi + zi * zi;

        // d^2 = |p_i|^2 - 2u ; dist = sqrt(max(d^2, 0))
        float d1 = sqrtf(fmaxf(fmaf(-2.0f, m2, sqi), 0.0f));
        float d2 = sqrtf(fmaxf(fmaf(-2.0f, m3, sqi), 0.0f));
        float d3 = sqrtf(fmaxf(fmaf(-2.0f, m4, sqi), 0.0f));
        float mean = (d1 + d2 + d3) * (1.0f / 3.0f);
        float s = 0.001f * fmaxf(mean, 1e-5f);

        float qr = quat[4 * i + 0];
        float qx = quat[4 * i + 1];
        float qy = quat[4 * i + 2];
        float qz = quat[4 * i + 3];
        float inv = rsqrtf(qr * qr + qx * qx + qy * qy + qz * qz);
        qr *= inv; qx *= inv; qy *= inv; qz *= inv;

        float R00 = 1.0f - 2.0f * (qy * qy + qz * qz);
        float R01 = 2.0f * (qx * qy - qr * qz);
        float R02 = 2.0f * (qx * qz + qr * qy);
        float R10 = 2.0f * (qx * qy + qr * qz);
        float R11 = 1.0f - 2.0f * (qx * qx + qz * qz);
        float R12 = 2.0f * (qy * qz - qr * qx);
        float R20 = 2.0f * (qx * qz - qr * qy);
        float R21 = 2.0f * (qy * qz + qr * qx);
        float R22 = 1.0f - 2.0f * (qx * qx + qy * qy);

        float M00 = s * R00, M01 = s * R01, M02 = s * R02;
        float M10 = s * R10, M11 = s * R11, M12 = s * R12;
        float M20 = s * R20, M21 = s * R21, M22 = s * R22;

        float c00 = M00 * M00 + M01 * M01 + M02 * M02;
        float c01 = M00 * M10 + M01 * M11 + M02 * M12;
        float c02 = M00 * M20 + M01 * M21 + M02 * M22;
        float c11 = M10 * M10 + M11 * M11 + M12 * M12;
        float c12 = M10 * M20 + M11 * M21 + M12 * M22;
        float c22 = M20 * M20 + M21 * M21 + M22 * M22;

        float* o = out + (size_t)i * 9;
        o[0] = c00; o[1] = c01; o[2] = c02;
        o[3] = c01; o[4] = c11; o[5] = c12;
        o[6] = c02; o[7] = c12; o[8] = c22;
    }

    if (threadIdx.x == 0) g_cnt[tile] = 0;   // reset for next graph replay
}

extern "C" void kernel_launch(void* const* d_in, const int* in_sizes, int n_in,
                              void* d_out, int out_size) {
    const float* pts  = (const float*)d_in[0];   // (N, 3) float32
    const float* quat = (const float*)d_in[1];   // (N, 4) float32
    float* out = (float*)d_out;                  // (N, 3, 3) float32
    int n = in_sizes[0] / 3;                     // 12288

    dim3 grid(GRIDX, JS);
    gauss_kernel<<<grid, TPB>>>(pts, quat, out, n);
}

// round 3
// speedup vs baseline: 1.2059x; 1.0708x over previous
#include <cuda_runtime.h>
#include <cuda_bf16.h>
#include <math.h>

// Fixed shapes: N = 12288
#define N_FIX   12288
#define JS      24            // j-splits
#define JT      512           // N / JS
#define TPB     128
#define TILE_I  256           // i's per block (2 per thread)
#define GRIDX   48            // N / TILE_I
#define NEG_BIG (-1.0e30f)

// Scratch: per (split, i) sorted top-4 of u = p_i.p_j - 0.5|p_j|^2 (desc).
// Non-self splits leave slot 4 = NEG_BIG (still a valid sorted 4-list).
__device__ float4 g_cand[JS * N_FIX];
// Per-i-tile arrival counters for the fused merge (reset each replay by the merger).
__device__ int g_cnt[GRIDX];

// ---- branchless selection networks --------------------------------------

__device__ __forceinline__ void sort4_top3(float u0, float u1, float u2, float u3,
                                           float& s1, float& s2, float& s3) {
    float p1 = fmaxf(u0, u1), p2 = fminf(u0, u1);
    float q1 = fmaxf(u2, u3), q2 = fminf(u2, u3);
    s1 = fmaxf(p1, q1);
    float x = fminf(p1, q1);
    float y = fmaxf(p2, q2);
    s2 = fmaxf(x, y);
    s3 = fminf(x, y);
}

__device__ __forceinline__ void sort4_full(float u0, float u1, float u2, float u3,
                                           float& s1, float& s2, float& s3, float& s4) {
    float p1 = fmaxf(u0, u1), p2 = fminf(u0, u1);
    float q1 = fmaxf(u2, u3), q2 = fminf(u2, u3);
    s1 = fmaxf(p1, q1);
    float x = fminf(p1, q1);
    float y = fmaxf(p2, q2);
    s2 = fmaxf(x, y);
    s3 = fminf(x, y);
    s4 = fminf(p2, q2);          // min of the two pair-losers = overall min
}

// merge sorted m1>=m2>=m3 with sorted s1>=s2>=s3, keep top-3 (7 min/max)
__device__ __forceinline__ void merge3(float& m1, float& m2, float& m3,
                                       float s1, float s2, float s3) {
    float a = fmaxf(m1, s1), b = fminf(m1, s1);
    float c = fmaxf(m2, s2);
    float e = fmaxf(m3, s3);
    float t = fminf(b, c);
    m1 = a;
    m2 = fmaxf(b, c);
    m3 = fmaxf(t, e);
}

// merge sorted 4-lists, keep top-4 (13 min/max)
__device__ __forceinline__ void merge4(float& m1, float& m2, float& m3, float& m4,
                                       float s1, float s2, float s3, float s4) {
    float a = fmaxf(m1, s1), b = fminf(m1, s1);
    float c = fmaxf(m2, s2), d = fminf(m2, s2);
    float e = fmaxf(m3, s3);
    float g = fmaxf(m4, s4);
    float t  = fminf(b, c);
    float r2 = fmaxf(b, c);
    float r3 = fmaxf(t, e);
    float l1 = fminf(t, e);
    m1 = a;
    m2 = r2;
    m3 = r3;
    m4 = fmaxf(fmaxf(l1, d), g);
}

__device__ __forceinline__ float dot_u(float x, float y, float z, float4 p) {
    return fmaf(z, p.z, fmaf(y, p.y, fmaf(x, p.x, -p.w)));
}

// ---- fused kernel: partial top-k + last-block merge + covariance --------

__global__ __launch_bounds__(TPB, 8)
void gauss_kernel(const float* __restrict__ pts,
                  const float* __restrict__ quat,
                  float* __restrict__ out, int n) {
    __shared__ float4 sh[JT];
    const int tile = blockIdx.x;
    const int sp   = blockIdx.y;
    const int j0   = sp * JT;
    const int i0   = tile * TILE_I + threadIdx.x;
    const int i1   = i0 + TPB;

    // Stage this split's points as {x, y, z, 0.5|p|^2}
    for (int t = threadIdx.x; t < JT; t += TPB) {
        int j = j0 + t;
        float x = pts[3 * j + 0];
        float y = pts[3 * j + 1];
        float z = pts[3 * j + 2];
        sh[t] = make_float4(x, y, z, 0.5f * (x * x + y * y + z * z));
    }
    __syncthreads();

    const float xa = pts[3 * i0 + 0], ya = pts[3 * i0 + 1], za = pts[3 * i0 + 2];
    const float xb = pts[3 * i1 + 0], yb = pts[3 * i1 + 1], zb = pts[3 * i1 + 2];

    float a1 = NEG_BIG, a2 = NEG_BIG, a3 = NEG_BIG, a4 = NEG_BIG;
    float b1 = NEG_BIG, b2 = NEG_BIG, b3 = NEG_BIG, b4 = NEG_BIG;

    // 256-wide i-tile always fully inside one 512-wide j-split: uniform branch.
    const bool hasSelf = ((tile >> 1) == sp);

    if (hasSelf) {
        // Track top-4: self (global max of u) is dropped at merge time.
        #pragma unroll 2
        for (int t = 0; t < JT; t += 4) {
            float4 p0 = sh[t], p1 = sh[t + 1], p2 = sh[t + 2], p3 = sh[t + 3];
            {
                float u0 = dot_u(xa, ya, za, p0), u1 = dot_u(xa, ya, za, p1);
                float u2 = dot_u(xa, ya, za, p2), u3 = dot_u(xa, ya, za, p3);
                float s1, s2, s3, s4;
                sort4_full(u0, u1, u2, u3, s1, s2, s3, s4);
                merge4(a1, a2, a3, a4, s1, s2, s3, s4);
            }
            {
                float u0 = dot_u(xb, yb, zb, p0), u1 = dot_u(xb, yb, zb, p1);
                float u2 = dot_u(xb, yb, zb, p2), u3 = dot_u(xb, yb, zb, p3);
                float s1, s2, s3, s4;
                sort4_full(u0, u1, u2, u3, s1, s2, s3, s4);
                merge4(b1, b2, b3, b4, s1, s2, s3, s4);
            }
        }
    } else {
        #pragma unroll 4
        for (int t = 0; t < JT; t += 4) {
            float4 p0 = sh[t], p1 = sh[t + 1], p2 = sh[t + 2], p3 = sh[t + 3];
            {
                float u0 = dot_u(xa, ya, za, p0), u1 = dot_u(xa, ya, za, p1);
                float u2 = dot_u(xa, ya, za, p2), u3 = dot_u(xa, ya, za, p3);
                float s1, s2, s3;
                sort4_top3(u0, u1, u2, u3, s1, s2, s3);
                merge3(a1, a2, a3, s1, s2, s3);
            }
            {
                float u0 = dot_u(xb, yb, zb, p0), u1 = dot_u(xb, yb, zb, p1);
                float u2 = dot_u(xb, yb, zb, p2), u3 = dot_u(xb, yb, zb, p3);
                float s1, s2, s3;
                sort4_top3(u0, u1, u2, u3, s1, s2, s3);
                merge3(b1, b2, b3, s1, s2, s3);
            }
        }
    }

    g_cand[sp * n + i0] = make_float4(a1, a2, a3, a4);
    g_cand[sp * n + i1] = make_float4(b1, b2, b3, b4);

    // ---- last block per i-tile performs the merge + covariance ----
    __threadfence();                       // release g_cand writes
    __shared__ int s_last;
    if (threadIdx.x == 0)
        s_last = (atomicAdd(&g_cnt[tile], 1) == JS - 1) ? 1 : 0;
    __syncthreads();
    if (!s_last) return;
    __threadfence();                       // acquire other blocks' g_cand

    #pragma unroll
    for (int k = 0; k < 2; ++k) {
        const int i = tile * TILE_I + threadIdx.x + k * TPB;

        float4 c0 = g_cand[0 * n + i];
        float m1 = c0.x, m2 = c0.y, m3 = c0.z, m4 = c0.w;
        #pragma unroll
        for (int s = 1; s < JS; ++s) {
            float4 c = g_cand[s * n + i];
            merge4(m1, m2, m3, m4, c.x, c.y, c.z, c.w);
        }
        // m1 == self (u_self = 0.5|p_i|^2 is the strict global max); NNs: m2..m4

        const float xi = pts[3 * i + 0];
        const float yi = pts[3 * i + 1];
        const float zi = pts[3 * i + 2];
        const float sqi = xi * xi + yi * yi + zi * zi;

        // d^2 = |p_i|^2 - 2u ; dist = sqrt(max(d^2, 0))
        float d1 = sqrtf(fmaxf(fmaf(-2.0f, m2, sqi), 0.0f));
        float d2 = sqrtf(fmaxf(fmaf(-2.0f, m3, sqi), 0.0f));
        float d3 = sqrtf(fmaxf(fmaf(-2.0f, m4, sqi), 0.0f));
        float mean = (d1 + d2 + d3) * (1.0f / 3.0f);
        float s = 0.001f * fmaxf(mean, 1e-5f);

        float qr = quat[4 * i + 0];
        float qx = quat[4 * i + 1];
        float qy = quat[4 * i + 2];
        float qz = quat[4 * i + 3];
        float inv = rsqrtf(qr * qr + qx * qx + qy * qy + qz * qz);
        qr *= inv; qx *= inv; qy *= inv; qz *= inv;

        float R00 = 1.0f - 2.0f * (qy * qy + qz * qz);
        float R01 = 2.0f * (qx * qy - qr * qz);
        float R02 = 2.0f * (qx * qz + qr * qy);
        float R10 = 2.0f * (qx * qy + qr * qz);
        float R11 = 1.0f - 2.0f * (qx * qx + qz * qz);
        float R12 = 2.0f * (qy * qz - qr * qx);
        float R20 = 2.0f * (qx * qz - qr * qy);
        float R21 = 2.0f * (qy * qz + qr * qx);
        float R22 = 1.0f - 2.0f * (qx * qx + qy * qy);

        float M00 = s * R00, M01 = s * R01, M02 = s * R02;
        float M10 = s * R10, M11 = s * R11, M12 = s * R12;
        float M20 = s * R20, M21 = s * R21, M22 = s * R22;

        float c00 = M00 * M00 + M01 * M01 + M02 * M02;
        float c01 = M00 * M10 + M01 * M11 + M02 * M12;
        float c02 = M00 * M20 + M01 * M21 + M02 * M22;
        float c11 = M10 * M10 + M11 * M11 + M12 * M12;
        float c12 = M10 * M20 + M11 * M21 + M12 * M22;
        float c22 = M20 * M20 + M21 * M21 + M22 * M22;

        float* o = out + (size_t)i * 9;
        o[0] = c00; o[1] = c01; o[2] = c02;
        o[3] = c01; o[4] = c11; o[5] = c12;
        o[6] = c02; o[7] = c12; o[8] = c22;
    }

    if (threadIdx.x == 0) g_cnt[tile] = 0;   // reset for next graph replay
}

extern "C" void kernel_launch(void* const* d_in, const int* in_sizes, int n_in,
                              void* d_out, int out_size) {
    const float* pts  = (const float*)d_in[0];   // (N, 3) float32
    const float* quat = (const float*)d_in[1];   // (N, 4) float32
    float* out = (float*)d_out;                  // (N, 3, 3) float32
    int n = in_sizes[0] / 3;                     // 12288

    dim3 grid(GRIDX, JS);
    gauss_kernel<<<grid, TPB>>>(pts, quat, out, n);
}